// round 1
// baseline (speedup 1.0000x reference)
#include <cuda_runtime.h>
#include <cuda_bf16.h>

#define NNODES 100000
#define NEDGES 3200000
#define NGRAPHS 128
#define F 32

// ---------------- scratch (static device globals; no allocation) ----------------
__device__ int   g_cnt[NNODES];        // per-dst edge count (histogram)
__device__ int   g_cur[NNODES];        // placement cursors
__device__ int   g_rowptr[NNODES + 1]; // CSR row pointers (by dst)
__device__ int   g_col[NEDGES];        // CSR: src index per slot
__device__ float g_dinv[NNODES];       // 1/sqrt(deg+1)
__device__ float g_s[NNODES];          // u0 = x * dinv (layer-1 scalar features)
__device__ float g_u1[NNODES * F];     // u = h * dinv ping
__device__ float g_u2[NNODES * F];     // pong
__device__ int   g_blocksums[128];
__device__ int   g_pool[NGRAPHS * F];  // int-keyed float max

// monotone float<->int key (works for negatives)
__device__ __forceinline__ int fkey(int i) { return i >= 0 ? i : (i ^ 0x7FFFFFFF); }
// key(-inf) = 0xFF800000 ^ 0x7FFFFFFF
#define KEY_NEG_INF 0x807FFFFF

// ---------------- init ----------------
__global__ void k_init() {
    int i = blockIdx.x * blockDim.x + threadIdx.x;
    if (i < NNODES) g_cnt[i] = 0;
    if (i < NGRAPHS * F) g_pool[i] = KEY_NEG_INF;
}

// ---------------- degree histogram ----------------
__global__ void k_hist(const int* __restrict__ dst, int E) {
    int i = blockIdx.x * blockDim.x + threadIdx.x;
    if (i < E) atomicAdd(&g_cnt[dst[i]], 1);
}

// ---------------- scan: block sums ----------------
__global__ void k_scan_bsum() {
    __shared__ int sh[1024];
    int t = threadIdx.x;
    int i = blockIdx.x * 1024 + t;
    sh[t] = (i < NNODES) ? g_cnt[i] : 0;
    __syncthreads();
    for (int off = 512; off > 0; off >>= 1) {
        if (t < off) sh[t] += sh[t + off];
        __syncthreads();
    }
    if (t == 0) g_blocksums[blockIdx.x] = sh[0];
}

// ---------------- scan: serial scan of block sums (tiny) ----------------
__global__ void k_scan_top(int nb) {
    if (threadIdx.x == 0) {
        int acc = 0;
        for (int i = 0; i < nb; i++) { int v = g_blocksums[i]; g_blocksums[i] = acc; acc += v; }
    }
}

// ---------------- scan: write rowptr + dinv + u0 + cursors ----------------
__global__ void k_scan_write(const float* __restrict__ x) {
    __shared__ int sh[1024];
    int t = threadIdx.x;
    int i = blockIdx.x * 1024 + t;
    int v = (i < NNODES) ? g_cnt[i] : 0;
    sh[t] = v;
    __syncthreads();
    // Hillis-Steele inclusive scan
    for (int off = 1; off < 1024; off <<= 1) {
        int add = (t >= off) ? sh[t - off] : 0;
        __syncthreads();
        sh[t] += add;
        __syncthreads();
    }
    int excl = sh[t] - v + g_blocksums[blockIdx.x];
    if (i < NNODES) {
        g_rowptr[i] = excl;
        g_cur[i]    = excl;
        float dn = rsqrtf((float)(v + 1));  // deg = in-edges + self-loop
        g_dinv[i] = dn;
        g_s[i]    = x[i] * dn;              // u0
        if (i == NNODES - 1) g_rowptr[NNODES] = excl + v;
    }
}

// ---------------- CSR placement ----------------
__global__ void k_place(const int* __restrict__ src, const int* __restrict__ dst, int E) {
    int i = blockIdx.x * blockDim.x + threadIdx.x;
    if (i < E) {
        int slot = atomicAdd(&g_cur[dst[i]], 1);
        g_col[slot] = src[i];
    }
}

// ---------------- layer 1: scalar propagate + rank-1 expand ----------------
__global__ void k_layer1(const float* __restrict__ w1, const float* __restrict__ b1) {
    int gtid = blockIdx.x * blockDim.x + threadIdx.x;
    int n = gtid >> 5;
    int lane = threadIdx.x & 31;
    if (n >= NNODES) return;
    int beg = g_rowptr[n], end = g_rowptr[n + 1];
    float acc = 0.f;
    for (int j = beg + lane; j < end; j += 32) acc += g_s[g_col[j]];
    #pragma unroll
    for (int off = 16; off > 0; off >>= 1) acc += __shfl_xor_sync(0xffffffffu, acc, off);
    float dn = g_dinv[n];
    float p = dn * (acc + g_s[n]);                 // propagate(x)[n]
    float h = fmaxf(fmaf(p, w1[lane], b1[lane]), 0.f);
    g_u1[n * F + lane] = h * dn;                   // store u = h*dinv
}

// ---------------- layers 2/3: vector propagate + 32x32 matmul ----------------
template <bool RELU, bool POOL>
__global__ void k_layer(const float* __restrict__ uin, float* __restrict__ uout,
                        const float* __restrict__ w, const float* __restrict__ b,
                        const int* __restrict__ batch) {
    __shared__ float wsh[F * F];
    for (int i = threadIdx.x; i < F * F; i += blockDim.x) wsh[i] = w[i];
    __syncthreads();

    int gtid = blockIdx.x * blockDim.x + threadIdx.x;
    int n = gtid >> 5;
    int lane = threadIdx.x & 31;
    if (n >= NNODES) return;

    int beg = g_rowptr[n], end = g_rowptr[n + 1];
    float acc = uin[n * F + lane];                 // self-loop term u[n]
    for (int j = beg; j < end; j += 32) {
        int jj = j + lane;
        int idx = (jj < end) ? g_col[jj] : -1;
        #pragma unroll
        for (int i = 0; i < 32; i++) {
            int s = __shfl_sync(0xffffffffu, idx, i);
            if (s < 0) break;                      // uniform: only tail has -1
            acc += uin[s * F + lane];              // coalesced 128B line
        }
    }
    float dn = g_dinv[n];
    float p = acc * dn;                            // propagate(h)[n, lane]

    // out[c] = sum_k p[k] * w[k][c] + b[c]  via warp shuffles
    float o = b[lane];
    #pragma unroll
    for (int k = 0; k < F; k++) {
        float pk = __shfl_sync(0xffffffffu, p, k);
        o = fmaf(pk, wsh[k * F + lane], o);
    }
    if (RELU) o = fmaxf(o, 0.f);
    if (POOL) {
        int g = batch[n];
        atomicMax(&g_pool[g * F + lane], fkey(__float_as_int(o)));
    } else {
        uout[n * F + lane] = o * dn;
    }
}

// ---------------- head: [G,32] -> relu(@wo1+bo1) -> @wo2+bo2 -> log_softmax ----------------
__global__ void k_head(const float* __restrict__ wo1, const float* __restrict__ bo1,
                       const float* __restrict__ wo2, const float* __restrict__ bo2,
                       float* __restrict__ out) {
    int g = threadIdx.x;
    if (g >= NGRAPHS) return;
    float gv[F];
    #pragma unroll
    for (int k = 0; k < F; k++) {
        int key = g_pool[g * F + k];
        gv[k] = __int_as_float(fkey(key));  // decode (involutive)
    }
    float h[16];
    #pragma unroll
    for (int j = 0; j < 16; j++) {
        float a = bo1[j];
        #pragma unroll
        for (int k = 0; k < F; k++) a = fmaf(gv[k], wo1[k * 16 + j], a);
        h[j] = fmaxf(a, 0.f);
    }
    float l0 = bo2[0], l1 = bo2[1];
    #pragma unroll
    for (int k = 0; k < 16; k++) { l0 = fmaf(h[k], wo2[k * 2], l0); l1 = fmaf(h[k], wo2[k * 2 + 1], l1); }
    float m = fmaxf(l0, l1);
    float lse = m + logf(expf(l0 - m) + expf(l1 - m));
    out[g * 2 + 0] = l0 - lse;
    out[g * 2 + 1] = l1 - lse;
}

// ---------------- launch ----------------
extern "C" void kernel_launch(void* const* d_in, const int* in_sizes, int n_in,
                              void* d_out, int out_size) {
    const float* x   = (const float*)d_in[0];
    const int*   ei  = (const int*)d_in[1];
    const int*   bat = (const int*)d_in[2];
    const float* w1  = (const float*)d_in[3];
    const float* b1  = (const float*)d_in[4];
    const float* w2  = (const float*)d_in[5];
    const float* b2  = (const float*)d_in[6];
    const float* w3  = (const float*)d_in[7];
    const float* b3  = (const float*)d_in[8];
    const float* wo1 = (const float*)d_in[9];
    const float* bo1 = (const float*)d_in[10];
    const float* wo2 = (const float*)d_in[11];
    const float* bo2 = (const float*)d_in[12];
    float* out = (float*)d_out;

    int E = in_sizes[1] / 2;
    const int* src = ei;
    const int* dst = ei + E;

    int nbScan = (NNODES + 1023) / 1024;              // 98
    int nbNode = (NNODES + 255) / 256;
    int nbEdge = (E + 255) / 256;
    int nbWarp = (NNODES * 32 + 255) / 256;           // warp-per-node kernels

    k_init<<<nbNode, 256>>>();
    k_hist<<<nbEdge, 256>>>(dst, E);
    k_scan_bsum<<<nbScan, 1024>>>();
    k_scan_top<<<1, 32>>>(nbScan);
    k_scan_write<<<nbScan, 1024>>>(x);
    k_place<<<nbEdge, 256>>>(src, dst, E);
    k_layer1<<<nbWarp, 256>>>(w1, b1);
    k_layer<true,  false><<<nbWarp, 256>>>(g_u1, g_u2, w2, b2, bat);
    k_layer<false, true ><<<nbWarp, 256>>>(g_u2, g_u1, w3, b3, bat);
    k_head<<<1, 128>>>(wo1, bo1, wo2, bo2, out);
}

// round 3
// speedup vs baseline: 1.2747x; 1.2747x over previous
#include <cuda_runtime.h>
#include <cuda_bf16.h>

#define NNODES 100000
#define NEDGES 3200000
#define NGRAPHS 128
#define F 32
#define SENT NNODES                     // sentinel node index (zero feature row)
#define COLCAP (NEDGES + 32 * NNODES)   // padded CSR capacity

// ---------------- scratch (static device globals; no allocation) ----------------
__device__ int   g_cnt[NNODES];          // per-dst in-degree (persists as deg)
__device__ int   g_cur[NNODES];          // placement cursors
__device__ int   g_rowptr[NNODES + 1];   // padded CSR row pointers (by dst)
__device__ int   g_col[COLCAP];          // CSR: src index per slot (padded w/ SENT)
__device__ float g_dinv[NNODES];         // 1/sqrt(deg+1)
__device__ float g_s[NNODES + 1];        // u0 = x * dinv (+ sentinel zero)
__device__ float g_u1[(NNODES + 1) * F]; // u = h * dinv ping (+ sentinel row)
__device__ float g_u2[(NNODES + 1) * F]; // pong
__device__ int   g_blocksums[128];
__device__ int   g_pool[NGRAPHS * F];    // int-keyed float max

__device__ __forceinline__ int fkey(int i) { return i >= 0 ? i : (i ^ 0x7FFFFFFF); }
#define KEY_NEG_INF 0x807FFFFF

// ---------------- init ----------------
__global__ void k_init() {
    int i = blockIdx.x * blockDim.x + threadIdx.x;
    if (i < NNODES) g_cnt[i] = 0;
    if (i < NGRAPHS * F) g_pool[i] = KEY_NEG_INF;
    if (i < F) {               // zero sentinel feature rows
        g_u1[SENT * F + i] = 0.f;
        g_u2[SENT * F + i] = 0.f;
        if (i == 0) g_s[SENT] = 0.f;
    }
}

// ---------------- degree histogram ----------------
__global__ void k_hist(const int* __restrict__ dst, int E) {
    int i = blockIdx.x * blockDim.x + threadIdx.x;
    if (i < E) atomicAdd(&g_cnt[dst[i]], 1);
}

// ---------------- scan phase A: per-block sums of PADDED counts ----------------
__global__ void k_scan_bsum() {
    __shared__ int sh[1024];
    int t = threadIdx.x;
    int i = blockIdx.x * 1024 + t;
    int v = (i < NNODES) ? g_cnt[i] : 0;
    sh[t] = (v + 31) & ~31;
    __syncthreads();
    for (int off = 512; off > 0; off >>= 1) {
        if (t < off) sh[t] += sh[t + off];
        __syncthreads();
    }
    if (t == 0) g_blocksums[blockIdx.x] = sh[0];
}

// ---------------- scan phase B: exclusive scan of block sums (parallel) ----------------
__global__ void k_scan_top(int nb) {
    __shared__ int sh[128];
    int t = threadIdx.x;
    int v = (t < nb) ? g_blocksums[t] : 0;
    sh[t] = v;
    __syncthreads();
    for (int off = 1; off < 128; off <<= 1) {
        int add = (t >= off) ? sh[t - off] : 0;
        __syncthreads();
        sh[t] += add;
        __syncthreads();
    }
    if (t < nb) g_blocksums[t] = sh[t] - v;  // exclusive
}

// ---------------- scan phase C: rowptr(+padded) + dinv + u0 + cursors ----------------
__global__ void k_scan_write(const float* __restrict__ x) {
    __shared__ int sh[1024];
    int t = threadIdx.x;
    int i = blockIdx.x * 1024 + t;
    int deg = (i < NNODES) ? g_cnt[i] : 0;
    int pv = (deg + 31) & ~31;
    sh[t] = pv;
    __syncthreads();
    for (int off = 1; off < 1024; off <<= 1) {
        int add = (t >= off) ? sh[t - off] : 0;
        __syncthreads();
        sh[t] += add;
        __syncthreads();
    }
    int excl = sh[t] - pv + g_blocksums[blockIdx.x];
    if (i < NNODES) {
        g_rowptr[i] = excl;
        g_cur[i]    = excl;
        float dn = rsqrtf((float)(deg + 1));
        g_dinv[i] = dn;
        g_s[i]    = x[i] * dn;
        if (i == NNODES - 1) g_rowptr[NNODES] = excl + pv;
    }
}

// ---------------- CSR placement ----------------
__global__ void k_place(const int* __restrict__ src, const int* __restrict__ dst, int E) {
    int i = blockIdx.x * blockDim.x + threadIdx.x;
    if (i < E) {
        int slot = atomicAdd(&g_cur[dst[i]], 1);
        g_col[slot] = src[i];
    }
}

// ---------------- fill padding slots with sentinel ----------------
__global__ void k_fill() {
    int gtid = blockIdx.x * blockDim.x + threadIdx.x;
    int n = gtid >> 5;
    int lane = threadIdx.x & 31;
    if (n >= NNODES) return;
    int start = g_rowptr[n] + g_cnt[n];   // first pad slot
    int end   = g_rowptr[n + 1];          // pad count < 32
    int j = start + lane;
    if (j < end) g_col[j] = SENT;
}

// ---------------- layer 1: scalar propagate + rank-1 expand ----------------
__global__ void k_layer1(const float* __restrict__ w1, const float* __restrict__ b1) {
    int gtid = blockIdx.x * blockDim.x + threadIdx.x;
    int n = gtid >> 5;
    int lane = threadIdx.x & 31;
    if (n >= NNODES) return;
    int beg = g_rowptr[n], end = g_rowptr[n + 1];
    float acc = 0.f;
    for (int j = beg + lane; j < end; j += 32)    // padded: no guard on g_s index
        acc += g_s[g_col[j]];
    #pragma unroll
    for (int off = 16; off > 0; off >>= 1) acc += __shfl_xor_sync(0xffffffffu, acc, off);
    float dn = g_dinv[n];
    float p = dn * (acc + g_s[n]);
    float h = fmaxf(fmaf(p, w1[lane], b1[lane]), 0.f);
    g_u1[n * F + lane] = h * dn;
}

// ---------------- layers 2/3: branch-free high-MLP gather + 32x32 matmul ----------------
template <bool RELU, bool POOL>
__global__ void k_layer(const float* __restrict__ uin, float* __restrict__ uout,
                        const float* __restrict__ w, const float* __restrict__ b,
                        const int* __restrict__ batch) {
    __shared__ float wsh[F * F];
    for (int i = threadIdx.x; i < F * F; i += blockDim.x) wsh[i] = w[i];
    __syncthreads();

    int gtid = blockIdx.x * blockDim.x + threadIdx.x;
    int n = gtid >> 5;
    int lane = threadIdx.x & 31;
    if (n >= NNODES) return;

    int beg = g_rowptr[n], end = g_rowptr[n + 1];
    float a0 = 0.f, a1 = 0.f, a2 = 0.f, a3 = 0.f;
    float a4 = 0.f, a5 = 0.f, a6 = 0.f, a7 = 0.f;
    for (int j = beg; j < end; j += 32) {
        const int4* cp = (const int4*)(g_col + j);  // warp-uniform, 16B-aligned
        #pragma unroll
        for (int q = 0; q < 4; q++) {
            int4 i0 = cp[q * 2 + 0];
            int4 i1 = cp[q * 2 + 1];
            a0 += uin[i0.x * F + lane];
            a1 += uin[i0.y * F + lane];
            a2 += uin[i0.z * F + lane];
            a3 += uin[i0.w * F + lane];
            a4 += uin[i1.x * F + lane];
            a5 += uin[i1.y * F + lane];
            a6 += uin[i1.z * F + lane];
            a7 += uin[i1.w * F + lane];
        }
    }
    float acc = ((a0 + a1) + (a2 + a3)) + ((a4 + a5) + (a6 + a7)) + uin[n * F + lane];
    float dn = g_dinv[n];
    float p = acc * dn;

    float o = b[lane];
    #pragma unroll
    for (int k = 0; k < F; k++) {
        float pk = __shfl_sync(0xffffffffu, p, k);
        o = fmaf(pk, wsh[k * F + lane], o);
    }
    if (RELU) o = fmaxf(o, 0.f);
    if (POOL) {
        int g = batch[n];
        atomicMax(&g_pool[g * F + lane], fkey(__float_as_int(o)));
    } else {
        uout[n * F + lane] = o * dn;
    }
}

// ---------------- head ----------------
__global__ void k_head(const float* __restrict__ wo1, const float* __restrict__ bo1,
                       const float* __restrict__ wo2, const float* __restrict__ bo2,
                       float* __restrict__ out) {
    int g = threadIdx.x;
    if (g >= NGRAPHS) return;
    float gv[F];
    #pragma unroll
    for (int k = 0; k < F; k++) gv[k] = __int_as_float(fkey(g_pool[g * F + k]));
    float h[16];
    #pragma unroll
    for (int j = 0; j < 16; j++) {
        float a = bo1[j];
        #pragma unroll
        for (int k = 0; k < F; k++) a = fmaf(gv[k], wo1[k * 16 + j], a);
        h[j] = fmaxf(a, 0.f);
    }
    float l0 = bo2[0], l1 = bo2[1];
    #pragma unroll
    for (int k = 0; k < 16; k++) { l0 = fmaf(h[k], wo2[k * 2], l0); l1 = fmaf(h[k], wo2[k * 2 + 1], l1); }
    float m = fmaxf(l0, l1);
    float lse = m + logf(expf(l0 - m) + expf(l1 - m));
    out[g * 2 + 0] = l0 - lse;
    out[g * 2 + 1] = l1 - lse;
}

// ---------------- launch ----------------
extern "C" void kernel_launch(void* const* d_in, const int* in_sizes, int n_in,
                              void* d_out, int out_size) {
    const float* x   = (const float*)d_in[0];
    const int*   ei  = (const int*)d_in[1];
    const int*   bat = (const int*)d_in[2];
    const float* w1  = (const float*)d_in[3];
    const float* b1  = (const float*)d_in[4];
    const float* w2  = (const float*)d_in[5];
    const float* b2  = (const float*)d_in[6];
    const float* w3  = (const float*)d_in[7];
    const float* b3  = (const float*)d_in[8];
    const float* wo1 = (const float*)d_in[9];
    const float* bo1 = (const float*)d_in[10];
    const float* wo2 = (const float*)d_in[11];
    const float* bo2 = (const float*)d_in[12];
    float* out = (float*)d_out;

    int E = in_sizes[1] / 2;
    const int* src = ei;
    const int* dst = ei + E;

    int nbScan = (NNODES + 1023) / 1024;              // 98
    int nbNode = (NNODES + 255) / 256;
    int nbEdge = (E + 255) / 256;
    int nbWarp = (NNODES * 32 + 255) / 256;

    k_init<<<nbNode, 256>>>();
    k_hist<<<nbEdge, 256>>>(dst, E);
    k_scan_bsum<<<nbScan, 1024>>>();
    k_scan_top<<<1, 128>>>(nbScan);
    k_scan_write<<<nbScan, 1024>>>(x);
    k_place<<<nbEdge, 256>>>(src, dst, E);
    k_fill<<<nbWarp, 256>>>();
    k_layer1<<<nbWarp, 256>>>(w1, b1);
    k_layer<true,  false><<<nbWarp, 256>>>(g_u1, g_u2, w2, b2, bat);
    k_layer<false, true ><<<nbWarp, 256>>>(g_u2, g_u1, w3, b3, bat);
    k_head<<<1, 128>>>(wo1, bo1, wo2, bo2, out);
}